// round 8
// baseline (speedup 1.0000x reference)
#include <cuda_runtime.h>
#include <cuda_bf16.h>
#include <math.h>

#define N_NODES 4096
#define E_EDGES 131072
#define DIM     128
#define DIM2    256
#define SDIM    128
#define RDIM    8
#define LDIM    16
#define HIDD    64
#define TOPKK   16
#define NEGV    (-1000000000.0f)

// ----------------- scratch (device globals; no allocation) ---------------
__device__ float    g_agg1[N_NODES*DIM];
__device__ float    g_hloc[N_NODES*DIM2];
__device__ float    g_hid [N_NODES*HIDD];
__device__ float    g_m   [N_NODES];
__device__ int      g_mf  [N_NODES];
__device__ int      g_vlist[N_NODES];
__device__ int      g_Nv;
__device__ float    g_qkp[N_NODES*512];     // [q | k | P1 | P2] per valid row
__device__ float    g_S [N_NODES*N_NODES];
__device__ int      g_vdc[N_NODES*TOPKK];
__device__ int      g_vdo[N_NODES*TOPKK];
__device__ float    g_sc [N_NODES*TOPKK];
__device__ float    g_ex [N_NODES*TOPKK];
__device__ float    g_shd[N_NODES*TOPKK];
__device__ float    g_rf [N_NODES*TOPKK*RDIM];
__device__ unsigned g_maxenc[N_NODES];
__device__ float    g_den[N_NODES];
__device__ float    g_aggH[N_NODES*DIM2];
__device__ float    g_Wfl[DIM*DIM2];        // W_loc_out @ W_prod_loc
__device__ float    g_Wfh[DIM2*DIM2];       // W_h_out @ W_prod_h
__device__ float    g_Wcat[DIM*512];        // [Wq | Wk | Wa1[0:128] | Wa1[128:256]]
// CSR (dst-sorted incoming edge lists)
__device__ int      g_cnt[N_NODES];
__device__ int      g_off[N_NODES+1];
__device__ int      g_cur[N_NODES];
__device__ int      g_elist[E_EDGES];

// ----------------- helpers ---------------
__device__ __forceinline__ float wredsum(float v){
#pragma unroll
    for (int o=16;o>0;o>>=1) v += __shfl_xor_sync(0xffffffffu, v, o);
    return v;
}
__device__ __forceinline__ unsigned enc(float f){
    unsigned u=__float_as_uint(f);
    return (u&0x80000000u)? ~u : (u|0x80000000u);
}
__device__ __forceinline__ float dec(unsigned u){
    return (u&0x80000000u)? __uint_as_float(u & 0x7fffffffu) : __uint_as_float(~u);
}
__device__ __forceinline__ void red4(float* a, float x,float y,float z,float w){
    asm volatile("red.global.add.v4.f32 [%0], {%1,%2,%3,%4};"
                 :: "l"(a),"f"(x),"f"(y),"f"(z),"f"(w) : "memory");
}
__device__ __forceinline__ float sh_dot(float vx,float vy,float vz, const float* w){
    float n = sqrtf(vx*vx+vy*vy+vz*vz);
    float inv = 1.0f/(n+1e-9f);
    float x=vx*inv, y=vy*inv, z=vz*inv;
    return w[0]+w[1]*x+w[2]*y+w[3]*z
      + w[4]*x*x + w[5]*y*y + w[6]*z*z
      + w[7]*x*y + w[8]*x*z + w[9]*y*z
      + w[10]*x*x*x + w[11]*y*y*y + w[12]*z*z*z
      + w[13]*x*x*y + w[14]*y*y*z + w[15]*z*z*x;
}
__device__ __forceinline__ void split_tf32(float f, float& hi, float& lo){
    unsigned h; asm("cvt.rna.tf32.f32 %0, %1;" : "=r"(h) : "f"(f));
    float l = f - __uint_as_float(h);
    unsigned lu; asm("cvt.rna.tf32.f32 %0, %1;" : "=r"(lu) : "f"(l));
    hi = __uint_as_float(h); lo = __uint_as_float(lu);
}
#define MMA_TF32(c, a0,a1,a2,a3, b0,b1) \
  asm volatile("mma.sync.aligned.m16n8k8.row.col.f32.tf32.tf32.f32 " \
   "{%0,%1,%2,%3}, {%4,%5,%6,%7}, {%8,%9}, {%0,%1,%2,%3};" \
   : "+f"((c)[0]),"+f"((c)[1]),"+f"((c)[2]),"+f"((c)[3]) \
   : "r"(a0),"r"(a1),"r"(a2),"r"(a3),"r"(b0),"r"(b1))
#define F2U(x) __float_as_uint(x)

// ----------------- fill / reset (den, maxenc, cnt) ---------------
__global__ void fill_k(){
    int i = blockIdx.x*blockDim.x + threadIdx.x;
    if (i < N_NODES){
        g_den[i]=0.f; g_maxenc[i]=0x007FFFFFu; g_cnt[i]=0;
    }
}

// ----------------- CSR build ---------------
__global__ void hist_k(const int* __restrict__ ei){
    int e = blockIdx.x*256 + threadIdx.x;
    if (e < E_EDGES) atomicAdd(&g_cnt[ei[E_EDGES+e]], 1);
}
__global__ __launch_bounds__(1024) void scan_csr(){
    __shared__ int s[1024];
    int t = threadIdx.x;
    int b = t*4;
    int c0=g_cnt[b], c1=g_cnt[b+1], c2=g_cnt[b+2], c3=g_cnt[b+3];
    int c = c0+c1+c2+c3;
    s[t]=c; __syncthreads();
    for (int off=1; off<1024; off<<=1){
        int v = s[t];
        int add = (t>=off)? s[t-off] : 0;
        __syncthreads();
        s[t] = v+add;
        __syncthreads();
    }
    int o0 = s[t]-c;
    int o1=o0+c0, o2=o1+c1, o3=o2+c2;
    g_off[b]=o0; g_off[b+1]=o1; g_off[b+2]=o2; g_off[b+3]=o3;
    g_cur[b]=o0; g_cur[b+1]=o1; g_cur[b+2]=o2; g_cur[b+3]=o3;
    if (t==1023) g_off[N_NODES]=s[1023];
}
__global__ void scatter_k(const int* __restrict__ ei){
    int e = blockIdx.x*256 + threadIdx.x;
    if (e < E_EDGES){
        int d = ei[E_EDGES+e];
        int p = atomicAdd(&g_cur[d], 1);
        g_elist[p] = e;
    }
}

// ----------------- stage 1: per-node gather of local messages (no atomics) ------
__global__ __launch_bounds__(256) void gather1(
    const float* __restrict__ h, const int* __restrict__ ei,
    const float* __restrict__ esh, const float* __restrict__ ef,
    const float* __restrict__ Wlr, const float* __restrict__ wlsh)
{
    __shared__ float sW[RDIM*DIM];
    __shared__ float swsh[LDIM];
    int tid = threadIdx.x;
    for (int i=tid;i<RDIM*DIM;i+=256) sW[i]=Wlr[i];
    if (tid<LDIM) swsh[tid]=wlsh[tid];
    __syncthreads();
    int n = blockIdx.x*8 + (tid>>5);
    int lane = tid & 31;
    int beg = g_off[n], end = g_off[n+1];
    int base = lane<<2;
    float a0=0.f,a1=0.f,a2=0.f,a3=0.f;
    for (int idx=beg; idx<end; ++idx){
        int e = g_elist[idx];
        int src = ei[e];
        float t = (lane<LDIM)? esh[(size_t)e*LDIM+lane]*swsh[lane] : 0.f;
        float shd = wredsum(t);
        float efv = (lane<RDIM)? ef[(size_t)e*RDIM+lane] : 0.f;
        float g0=0.f,g1=0.f,g2=0.f,g3=0.f;
#pragma unroll
        for (int r=0;r<RDIM;r++){
            float er = __shfl_sync(0xffffffffu, efv, r);
            g0 += er*sW[r*DIM+base+0];
            g1 += er*sW[r*DIM+base+1];
            g2 += er*sW[r*DIM+base+2];
            g3 += er*sW[r*DIM+base+3];
        }
        float4 hv = *(const float4*)(h + (size_t)src*DIM + base);
        a0 += hv.x*g0*shd; a1 += hv.y*g1*shd;
        a2 += hv.z*g2*shd; a3 += hv.w*g3*shd;
    }
    *(float4*)&g_agg1[(size_t)n*DIM+base] = make_float4(a0,a1,a2,a3);
}

// ----------------- weight concat for fused qkP GEMM ---------------
__global__ void concat_w(const float* __restrict__ Wq, const float* __restrict__ Wk,
                         const float* __restrict__ Wa1){
    int i = blockIdx.x*256 + threadIdx.x;  // 0 .. 128*512-1
    int k = i >> 9, c = i & 511;
    float v;
    if (c < 128)      v = Wq[k*128 + c];
    else if (c < 256) v = Wk[k*128 + (c-128)];
    else if (c < 384) v = Wa1[k*128 + (c-256)];
    else              v = Wa1[(128+k)*128 + (c-384)];
    g_Wcat[i] = v;
}

// ----------------- tensor-core 3xTF32 GEMM (128x64 block, 8 warps, pre-split smem) --
enum { EPI_NONE=0, EPI_SCORES=1, EPI_ADDPADH=2, EPI_BIASRELU=3, EPI_QKP=4, EPI_FINAL=5 };

template<int EPI, bool TRANSB, bool GATHER>
__global__ __launch_bounds__(256)
void tcgemm(const float* __restrict__ A, int lda,
            const float* __restrict__ B, int ldb,
            float* __restrict__ C, int ldc,
            int M, int Nc, int K,
            const int* __restrict__ Mdyn,
            const int* __restrict__ gidx,
            const float* __restrict__ ep0,
            const float* __restrict__ ep1,
            float scale)
{
    if (Mdyn) M = *Mdyn;
    int NB = (EPI==EPI_SCORES) ? M : Nc;
    int by = blockIdx.y, bx = blockIdx.x;
    if (by*128 >= M || bx*64 >= NB) return;

    __shared__ float Ah[16][136], Al[16][136];
    __shared__ float Bh[16][72],  Bl[16][72];

    int tid = threadIdx.x;
    int warp = tid>>5, lane = tid&31;
    int wm = (warp&3)<<5, wn = (warp>>2)<<5;
    int gid = lane>>2, tg = lane&3;

    float acc[2][4][4];
#pragma unroll
    for (int i=0;i<2;i++)
#pragma unroll
        for (int j=0;j<4;j++)
#pragma unroll
            for (int k=0;k<4;k++) acc[i][j][k]=0.f;

    for (int k0=0; k0<K; k0+=16){
        // A tile 128x16 -> Ah/Al[k][m]
#pragma unroll
        for (int j=0;j<2;j++){
            int idx = tid + j*256;
            int row = idx & 127;
            int c4  = (idx >> 7) << 2;
            int gr = by*128 + row;
            float4 v = make_float4(0.f,0.f,0.f,0.f);
            if (gr < M){
                int ri = GATHER ? gidx[gr] : gr;
                v = *(const float4*)(A + (size_t)ri*lda + k0 + c4);
            }
            float hx,lx;
            split_tf32(v.x,hx,lx); Ah[c4+0][row]=hx; Al[c4+0][row]=lx;
            split_tf32(v.y,hx,lx); Ah[c4+1][row]=hx; Al[c4+1][row]=lx;
            split_tf32(v.z,hx,lx); Ah[c4+2][row]=hx; Al[c4+2][row]=lx;
            split_tf32(v.w,hx,lx); Ah[c4+3][row]=hx; Al[c4+3][row]=lx;
        }
        // B tile 16x64 -> Bh/Bl[k][n]
        if (!TRANSB){
            int kk = tid>>4, n4 = (tid&15)<<2;
            float4 v = *(const float4*)(B + (size_t)(k0+kk)*ldb + bx*64 + n4);
            float4 hv, lv;
            split_tf32(v.x,hv.x,lv.x); split_tf32(v.y,hv.y,lv.y);
            split_tf32(v.z,hv.z,lv.z); split_tf32(v.w,hv.w,lv.w);
            *(float4*)&Bh[kk][n4] = hv;
            *(float4*)&Bl[kk][n4] = lv;
        } else {
            int n = tid & 63;
            int c4 = (tid >> 6) << 2;
            int gn = bx*64 + n;
            float4 v = make_float4(0.f,0.f,0.f,0.f);
            if (gn < NB) v = *(const float4*)(B + (size_t)gn*ldb + k0 + c4);
            float hx,lx;
            split_tf32(v.x,hx,lx); Bh[c4+0][n]=hx; Bl[c4+0][n]=lx;
            split_tf32(v.y,hx,lx); Bh[c4+1][n]=hx; Bl[c4+1][n]=lx;
            split_tf32(v.z,hx,lx); Bh[c4+2][n]=hx; Bl[c4+2][n]=lx;
            split_tf32(v.w,hx,lx); Bh[c4+3][n]=hx; Bl[c4+3][n]=lx;
        }
        __syncthreads();
#pragma unroll
        for (int ks=0; ks<16; ks+=8){
            unsigned ahi[2][4], alo[2][4], bhi[4][2], blo[4][2];
#pragma unroll
            for (int mt=0;mt<2;mt++){
                int rb = wm + mt*16;
                ahi[mt][0]=F2U(Ah[ks+tg  ][rb+gid  ]); alo[mt][0]=F2U(Al[ks+tg  ][rb+gid  ]);
                ahi[mt][1]=F2U(Ah[ks+tg  ][rb+gid+8]); alo[mt][1]=F2U(Al[ks+tg  ][rb+gid+8]);
                ahi[mt][2]=F2U(Ah[ks+tg+4][rb+gid  ]); alo[mt][2]=F2U(Al[ks+tg+4][rb+gid  ]);
                ahi[mt][3]=F2U(Ah[ks+tg+4][rb+gid+8]); alo[mt][3]=F2U(Al[ks+tg+4][rb+gid+8]);
            }
#pragma unroll
            for (int nt=0;nt<4;nt++){
                int cb = wn + nt*8;
                bhi[nt][0]=F2U(Bh[ks+tg  ][cb+gid]); blo[nt][0]=F2U(Bl[ks+tg  ][cb+gid]);
                bhi[nt][1]=F2U(Bh[ks+tg+4][cb+gid]); blo[nt][1]=F2U(Bl[ks+tg+4][cb+gid]);
            }
#pragma unroll
            for (int mt=0;mt<2;mt++)
#pragma unroll
                for (int nt=0;nt<4;nt++){
                    MMA_TF32(acc[mt][nt], ahi[mt][0],ahi[mt][1],ahi[mt][2],ahi[mt][3], bhi[nt][0],bhi[nt][1]);
                    MMA_TF32(acc[mt][nt], ahi[mt][0],ahi[mt][1],ahi[mt][2],ahi[mt][3], blo[nt][0],blo[nt][1]);
                    MMA_TF32(acc[mt][nt], alo[mt][0],alo[mt][1],alo[mt][2],alo[mt][3], bhi[nt][0],bhi[nt][1]);
                }
        }
        __syncthreads();
    }

#pragma unroll
    for (int mt=0;mt<2;mt++){
#pragma unroll
        for (int nt=0;nt<4;nt++){
            int rb = by*128 + wm + mt*16 + gid;
            int cb = bx*64 + wn + nt*8 + (tg<<1);
#pragma unroll
            for (int e=0;e<4;e++){
                int r = rb + ((e>=2)? 8:0);
                int c = cb + (e&1);
                if (r >= M || c >= NB) continue;
                float v = acc[mt][nt][e];
                if constexpr (EPI==EPI_SCORES){
                    v *= scale;
                    if (r==c) v = NEGV;
                } else if constexpr (EPI==EPI_ADDPADH){
                    if (c < DIM) v += ep0[(size_t)r*DIM + c];
                } else if constexpr (EPI==EPI_BIASRELU){
                    v += ep0[c]; v = v>0.f ? v : 0.f;
                } else if constexpr (EPI==EPI_QKP){
                    if (c >= 256 && c < 384) v += ep0[c-256];
                } else if constexpr (EPI==EPI_FINAL){
                    float hl = ep0[(size_t)r*DIM2 + c];
                    float mm = ep1[r];
                    float mfv = (mm > 0.5f) ? 1.f : 0.f;
                    v = (1.f-mm)*hl + mm*((v+hl)*mfv);
                }
                C[(size_t)r*ldc + c] = v;
            }
        }
    }
}

// ----------------- mask MLP output + sigmoid ---------------
__global__ void compute_m(const float* __restrict__ Wms2, const float* __restrict__ bms2)
{
    int row = blockIdx.x*4 + (threadIdx.x>>5);
    int lane = threadIdx.x & 31;
    if (row >= N_NODES) return;
    float s = g_hid[row*HIDD+lane]*Wms2[lane] + g_hid[row*HIDD+lane+32]*Wms2[lane+32];
    s = wredsum(s);
    if (lane==0){
        float z = s + bms2[0];
        float m = 1.f/(1.f+expf(-z));
        g_m[row] = m;
        g_mf[row] = (m > 0.5f) ? 1 : 0;
    }
}

// ----------------- ordered compaction of valid nodes ---------------
__global__ __launch_bounds__(1024) void scan_valid()
{
    __shared__ int cnt[1024];
    int t = threadIdx.x;
    int b = t*4;
    int l0=g_mf[b], l1=g_mf[b+1], l2=g_mf[b+2], l3=g_mf[b+3];
    int c = l0+l1+l2+l3;
    cnt[t]=c; __syncthreads();
    for (int off=1; off<1024; off<<=1){
        int v = cnt[t];
        int add = (t>=off)? cnt[t-off] : 0;
        __syncthreads();
        cnt[t] = v+add;
        __syncthreads();
    }
    int pos = cnt[t]-c;
    if (l0) g_vlist[pos++]=b;
    if (l1) g_vlist[pos++]=b+1;
    if (l2) g_vlist[pos++]=b+2;
    if (l3) g_vlist[pos++]=b+3;
    if (t==1023) g_Nv = cnt[1023];
}

// ----------------- per-row top-16 (tie -> lowest index, matches jax) ---------------
__global__ __launch_bounds__(128) void topk_k()
{
    int Nv = g_Nv;
    int vi = blockIdx.x;
    if (vi >= Nv) return;
    __shared__ float vals[N_NODES];
    __shared__ float rv[128];
    __shared__ int   ri[128];
    int tid = threadIdx.x;
    const float* row = &g_S[(size_t)vi*N_NODES];
    for (int j=tid;j<Nv;j+=128) vals[j]=row[j];
    __syncthreads();
    for (int t=0;t<TOPKK;t++){
        float bv=-3.4e38f; int bi=0x7fffffff;
        for (int j=tid;j<Nv;j+=128){
            float v=vals[j];
            if (v>bv || (v==bv && j<bi)){bv=v;bi=j;}
        }
        rv[tid]=bv; ri[tid]=bi;
        __syncthreads();
        for (int off=64;off>0;off>>=1){
            if (tid<off){
                float ov=rv[tid+off]; int oi=ri[tid+off];
                if (ov>rv[tid] || (ov==rv[tid] && oi<ri[tid])){rv[tid]=ov;ri[tid]=oi;}
            }
            __syncthreads();
        }
        if (tid==0){
            int bj = ri[0];
            if (rv[0] > NEGV*0.5f){
                g_vdc[vi*TOPKK+t]=bj;
                g_vdo[vi*TOPKK+t]=g_vlist[bj];
            } else {
                g_vdc[vi*TOPKK+t]=-1;
                g_vdo[vi*TOPKK+t]=-1;
            }
            vals[bj] = -3.4e38f;
        }
        __syncthreads();
    }
}

// ----------------- virtual edge MLP score ---------------
__global__ __launch_bounds__(256) void vedge_mlp(
    const float* __restrict__ pos, const float* __restrict__ Wa1,
    const float* __restrict__ Wa2, const float* __restrict__ ba2,
    const float* __restrict__ whsh)
{
    __shared__ float sW1[RDIM*SDIM];
    __shared__ float sW2[SDIM];
    int tid=threadIdx.x;
    for (int i=tid;i<RDIM*SDIM;i+=256) sW1[i]=Wa1[2*SDIM*SDIM + i];
    for (int i=tid;i<SDIM;i+=256) sW2[i]=Wa2[i];
    __syncthreads();
    int Nv = g_Nv;
    int s = blockIdx.x*8 + (tid>>5);
    int lane = tid & 31;
    if (s >= Nv*TOPKK) return;
    int jo = g_vdo[s];
    if (jo < 0) return;
    int vi = s >> 4;
    int jc = g_vdc[s];
    int i  = g_vlist[vi];
    float dx = pos[i*3+0]-pos[jo*3+0];
    float dy = pos[i*3+1]-pos[jo*3+1];
    float dz = pos[i*3+2]-pos[jo*3+2];
    float r = sqrtf(dx*dx+dy*dy+dz*dz);
    float rf[8];
#pragma unroll
    for (int k=0;k<8;k++){ float cc=k*(5.0f/7.0f); float d=r-cc; rf[k]=expf(-4.0f*d*d); }
    if (lane < 8){
        float cc=lane*(5.0f/7.0f); float d=r-cc;
        g_rf[s*RDIM+lane] = expf(-4.0f*d*d);
    }
    if (lane==0) g_shd[s] = sh_dot(dx,dy,dz, whsh);
    float sum = 0.f;
#pragma unroll
    for (int u=0;u<4;u++){
        int d = lane + u*32;
        float hv = g_qkp[(size_t)vi*512 + 256 + d] + g_qkp[(size_t)jc*512 + 384 + d];
#pragma unroll
        for (int k=0;k<8;k++) hv += rf[k]*sW1[k*SDIM+d];
        hv = hv>0.f ? hv : 0.f;
        sum += hv*sW2[d];
    }
    sum = wredsum(sum);
    if (lane==0){
        float sc = sum + ba2[0];
        g_sc[s] = sc;
        atomicMax(&g_maxenc[jo], enc(sc));
    }
}

// ----------------- softmax denominator ---------------
__global__ void softmax2()
{
    int s = blockIdx.x*blockDim.x + threadIdx.x;
    int Nv = g_Nv;
    if (s >= Nv*TOPKK) return;
    int jo = g_vdo[s];
    if (jo < 0) return;
    float mx = dec(g_maxenc[jo]);
    float e = expf(g_sc[s]-mx);
    g_ex[s] = e;
    atomicAdd(&g_den[jo], e);
}

// ----------------- real-edge hierarchical gather (per-node, no atomics) ----------
__global__ __launch_bounds__(256) void gatherH(
    const float* __restrict__ pos, const int* __restrict__ ei,
    const float* __restrict__ Whr, const float* __restrict__ whsh)
{
    __shared__ float sW[RDIM*DIM2];
    __shared__ float swsh[LDIM];
    int tid=threadIdx.x;
    for (int i=tid;i<RDIM*DIM2;i+=256) sW[i]=Whr[i];
    if (tid<LDIM) swsh[tid]=whsh[tid];
    __syncthreads();
    int n = blockIdx.x*8 + (tid>>5);
    int lane = tid & 31;
    int base = lane*8;
    float acc[8] = {0.f,0.f,0.f,0.f,0.f,0.f,0.f,0.f};
    if (g_mf[n]){
        int beg = g_off[n], end = g_off[n+1];
        float px = pos[n*3+0], py = pos[n*3+1], pz = pos[n*3+2];
        for (int idx=beg; idx<end; ++idx){
            int e = g_elist[idx];
            int src = ei[e];
            if (!g_mf[src]) continue;
            float dx = pos[src*3+0]-px;
            float dy = pos[src*3+1]-py;
            float dz = pos[src*3+2]-pz;
            float r = sqrtf(dx*dx+dy*dy+dz*dz);
            float shd = sh_dot(dx,dy,dz, swsh);
            float rf[8];
#pragma unroll
            for (int k=0;k<8;k++){ float cc=k*(5.0f/7.0f); float d=r-cc; rf[k]=expf(-4.0f*d*d); }
            float4 h0 = *(const float4*)&g_hloc[(size_t)src*DIM2+base];
            float4 h1 = *(const float4*)&g_hloc[(size_t)src*DIM2+base+4];
            float hv[8] = {h0.x,h0.y,h0.z,h0.w,h1.x,h1.y,h1.z,h1.w};
#pragma unroll
            for (int u=0;u<8;u++){
                float g=0.f;
#pragma unroll
                for (int k=0;k<8;k++) g += rf[k]*sW[k*DIM2+base+u];
                acc[u] += hv[u]*g*shd;
            }
        }
    }
    *(float4*)&g_aggH[(size_t)n*DIM2+base  ] = make_float4(acc[0],acc[1],acc[2],acc[3]);
    *(float4*)&g_aggH[(size_t)n*DIM2+base+4] = make_float4(acc[4],acc[5],acc[6],acc[7]);
}

// ----------------- virtual-edge hierarchical messages (atomics, low degree) ------
__global__ __launch_bounds__(256) void virt_msgs(const float* __restrict__ Whr)
{
    __shared__ float sW[RDIM*DIM2];
    int tid=threadIdx.x;
    for (int i=tid;i<RDIM*DIM2;i+=256) sW[i]=Whr[i];
    __syncthreads();
    int Nv = g_Nv;
    int s = blockIdx.x*8 + (tid>>5);
    int lane = tid & 31;
    if (s >= Nv*TOPKK) return;
    int jo = g_vdo[s];
    if (jo < 0) return;
    int vi = s >> 4;
    int i  = g_vlist[vi];
    float wv = g_ex[s]/(g_den[jo]+1e-12f);
    float shd = g_shd[s];
    float rf[8];
#pragma unroll
    for (int k=0;k<8;k++) rf[k]=g_rf[s*RDIM+k]*wv;
    int base = lane*8;
    float g[8];
#pragma unroll
    for (int u=0;u<8;u++){
        float acc=0.f;
#pragma unroll
        for (int k=0;k<8;k++) acc += rf[k]*sW[k*DIM2+base+u];
        g[u]=acc;
    }
    float4 h0 = *(const float4*)&g_hloc[(size_t)i*DIM2+base];
    float4 h1 = *(const float4*)&g_hloc[(size_t)i*DIM2+base+4];
    red4(&g_aggH[(size_t)jo*DIM2+base  ], h0.x*g[0]*shd, h0.y*g[1]*shd, h0.z*g[2]*shd, h0.w*g[3]*shd);
    red4(&g_aggH[(size_t)jo*DIM2+base+4], h1.x*g[4]*shd, h1.y*g[5]*shd, h1.z*g[6]*shd, h1.w*g[7]*shd);
}

// ----------------- launcher ---------------
extern "C" void kernel_launch(void* const* d_in, const int* in_sizes, int n_in,
                              void* d_out, int out_size)
{
    const float* h    = (const float*)d_in[0];
    const float* pos  = (const float*)d_in[1];
    const int*   ei   = (const int*)  d_in[2];
    const float* esh  = (const float*)d_in[3];
    const float* ef   = (const float*)d_in[4];
    const float* Wlr  = (const float*)d_in[6];
    const float* wlsh = (const float*)d_in[7];
    const float* Wlout= (const float*)d_in[8];
    const float* Wpl  = (const float*)d_in[9];
    const float* Wms1 = (const float*)d_in[10];
    const float* bms1 = (const float*)d_in[11];
    const float* Wms2 = (const float*)d_in[12];
    const float* bms2 = (const float*)d_in[13];
    const float* Wq   = (const float*)d_in[14];
    const float* Wk   = (const float*)d_in[15];
    const float* Wa1  = (const float*)d_in[16];
    const float* ba1  = (const float*)d_in[17];
    const float* Wa2  = (const float*)d_in[18];
    const float* ba2  = (const float*)d_in[19];
    const float* Whr  = (const float*)d_in[20];
    const float* whsh = (const float*)d_in[21];
    const float* Whout= (const float*)d_in[22];
    const float* Wph  = (const float*)d_in[23];
    float* out = (float*)d_out;

    float *p_agg1,*p_hloc,*p_hid,*p_qkp,*p_S,*p_aggH,*p_m,*p_Wfl,*p_Wfh,*p_Wcat;
    int *p_Nv,*p_vlist;
    cudaGetSymbolAddress((void**)&p_agg1, g_agg1);
    cudaGetSymbolAddress((void**)&p_hloc, g_hloc);
    cudaGetSymbolAddress((void**)&p_hid , g_hid );
    cudaGetSymbolAddress((void**)&p_qkp , g_qkp );
    cudaGetSymbolAddress((void**)&p_S   , g_S   );
    cudaGetSymbolAddress((void**)&p_aggH, g_aggH);
    cudaGetSymbolAddress((void**)&p_m   , g_m   );
    cudaGetSymbolAddress((void**)&p_Wfl , g_Wfl );
    cudaGetSymbolAddress((void**)&p_Wfh , g_Wfh );
    cudaGetSymbolAddress((void**)&p_Wcat, g_Wcat);
    cudaGetSymbolAddress((void**)&p_Nv  , g_Nv  );
    cudaGetSymbolAddress((void**)&p_vlist, g_vlist);

    const float scal = 0.088388347648318447f; // 1/sqrt(128)

    // CSR build + resets
    fill_k<<<16,256>>>();
    hist_k<<<E_EDGES/256,256>>>(ei);
    scan_csr<<<1,1024>>>();
    scatter_k<<<E_EDGES/256,256>>>(ei);

    // per-node local message gather (no atomics)
    gather1<<<N_NODES/8,256>>>(h,ei,esh,ef,Wlr,wlsh);

    // fused weights: Wfl = Wlout@Wpl, Wfh = Whout@Wph, Wcat = [Wq|Wk|Wa1a|Wa1b]
    tcgemm<EPI_NONE,false,false><<<dim3(4,1),256>>>(Wlout,DIM2, Wpl,DIM2, p_Wfl,DIM2,
        DIM,DIM2,DIM2, nullptr,nullptr,nullptr,nullptr,0.f);
    tcgemm<EPI_NONE,false,false><<<dim3(4,2),256>>>(Whout,DIM2, Wph,DIM2, p_Wfh,DIM2,
        DIM2,DIM2,DIM2, nullptr,nullptr,nullptr,nullptr,0.f);
    concat_w<<<256,256>>>(Wq,Wk,Wa1);

    // h_local = agg1 @ Wfl + pad(h)
    tcgemm<EPI_ADDPADH,false,false><<<dim3(4,32),256>>>(p_agg1,DIM, p_Wfl,DIM2, p_hloc,DIM2,
        N_NODES,DIM2,DIM, nullptr,nullptr, h,nullptr,0.f);
    // hidden = relu(h_scalar @ W_ms1 + b_ms1)
    tcgemm<EPI_BIASRELU,false,false><<<dim3(1,32),256>>>(p_hloc,DIM2, Wms1,HIDD, p_hid,HIDD,
        N_NODES,HIDD,SDIM, nullptr,nullptr, bms1,nullptr,0.f);
    compute_m<<<1024,128>>>(Wms2,bms2);
    scan_valid<<<1,1024>>>();
    // fused gathered GEMM: [q | k | P1(+bias) | P2] = hloc_valid @ Wcat
    tcgemm<EPI_QKP,false,true><<<dim3(8,32),256>>>(p_hloc,DIM2, p_Wcat,512, p_qkp,512,
        N_NODES,512,SDIM, p_Nv, p_vlist, ba1,nullptr,0.f);
    // scores = q @ k^T * scale, diag=NEG (compact Nv x Nv)
    tcgemm<EPI_SCORES,true,false><<<dim3(64,32),256>>>(p_qkp,512, p_qkp+SDIM,512, p_S,N_NODES,
        N_NODES,N_NODES,SDIM, p_Nv, nullptr, nullptr,nullptr, scal);
    topk_k<<<N_NODES,128>>>();
    vedge_mlp<<<N_NODES*TOPKK/8,256>>>(pos, Wa1, Wa2, ba2, whsh);
    softmax2<<<N_NODES*TOPKK/256,256>>>();
    // real-edge hierarchical gather (writes aggH), then virtual adds on top
    gatherH<<<N_NODES/8,256>>>(pos,ei,Whr,whsh);
    virt_msgs<<<N_NODES*TOPKK/8,256>>>(Whr);
    // out = (1-m)*h_local + m*((aggH@Wfh + h_local)*mf)
    tcgemm<EPI_FINAL,false,false><<<dim3(4,32),256>>>(p_aggH,DIM2, p_Wfh,DIM2, out,DIM2,
        N_NODES,DIM2,DIM2, nullptr,nullptr, p_hloc, p_m, 0.f);
}

// round 12
// speedup vs baseline: 1.2903x; 1.2903x over previous
#include <cuda_runtime.h>
#include <cuda_bf16.h>
#include <math.h>

#define N_NODES 4096
#define E_EDGES 131072
#define DIM     128
#define DIM2    256
#define SDIM    128
#define RDIM    8
#define LDIM    16
#define HIDD    64
#define TOPKK   16
#define NEGV    (-1000000000.0f)

// ----------------- scratch (device globals; no allocation) ---------------
__device__ float    g_agg1[N_NODES*DIM];
__device__ float    g_hloc[N_NODES*DIM2];
__device__ float    g_hid [N_NODES*HIDD];
__device__ float    g_m   [N_NODES];
__device__ int      g_mf  [N_NODES];
__device__ int      g_vlist[N_NODES];
__device__ int      g_Nv;
__device__ unsigned g_ticket;
__device__ float    g_qkp[N_NODES*512];     // [q | k | P1 | P2] per valid row
__device__ float    g_S [N_NODES*N_NODES];
__device__ int      g_vdc[N_NODES*TOPKK];
__device__ int      g_vdo[N_NODES*TOPKK];
__device__ float    g_sc [N_NODES*TOPKK];
__device__ float    g_ex [N_NODES*TOPKK];
__device__ float    g_shd[N_NODES*TOPKK];
__device__ float    g_rf [N_NODES*TOPKK*RDIM];
__device__ unsigned g_maxenc[N_NODES];
__device__ float    g_den[N_NODES];
__device__ float    g_aggH[N_NODES*DIM2];
__device__ float    g_Wfl[DIM*DIM2];        // W_loc_out @ W_prod_loc
__device__ float    g_Wfh[DIM2*DIM2];       // W_h_out @ W_prod_h
__device__ float    g_Wcat[DIM*512];        // [Wq | Wk | Wa1[0:128] | Wa1[128:256]]

// ----------------- helpers ---------------
__device__ __forceinline__ float wredsum(float v){
#pragma unroll
    for (int o=16;o>0;o>>=1) v += __shfl_xor_sync(0xffffffffu, v, o);
    return v;
}
__device__ __forceinline__ unsigned enc(float f){
    unsigned u=__float_as_uint(f);
    return (u&0x80000000u)? ~u : (u|0x80000000u);
}
__device__ __forceinline__ float dec(unsigned u){
    return (u&0x80000000u)? __uint_as_float(u & 0x7fffffffu) : __uint_as_float(~u);
}
__device__ __forceinline__ void red4(float* a, float x,float y,float z,float w){
    asm volatile("red.global.add.v4.f32 [%0], {%1,%2,%3,%4};"
                 :: "l"(a),"f"(x),"f"(y),"f"(z),"f"(w) : "memory");
}
__device__ __forceinline__ float sh_dot(float vx,float vy,float vz, const float* w){
    float n = sqrtf(vx*vx+vy*vy+vz*vz);
    float inv = 1.0f/(n+1e-9f);
    float x=vx*inv, y=vy*inv, z=vz*inv;
    return w[0]+w[1]*x+w[2]*y+w[3]*z
      + w[4]*x*x + w[5]*y*y + w[6]*z*z
      + w[7]*x*y + w[8]*x*z + w[9]*y*z
      + w[10]*x*x*x + w[11]*y*y*y + w[12]*z*z*z
      + w[13]*x*x*y + w[14]*y*y*z + w[15]*z*z*x;
}
__device__ __forceinline__ void split_tf32(float f, float& hi, float& lo){
    unsigned h; asm("cvt.rna.tf32.f32 %0, %1;" : "=r"(h) : "f"(f));
    float l = f - __uint_as_float(h);
    unsigned lu; asm("cvt.rna.tf32.f32 %0, %1;" : "=r"(lu) : "f"(l));
    hi = __uint_as_float(h); lo = __uint_as_float(lu);
}
#define MMA_TF32(c, a0,a1,a2,a3, b0,b1) \
  asm volatile("mma.sync.aligned.m16n8k8.row.col.f32.tf32.tf32.f32 " \
   "{%0,%1,%2,%3}, {%4,%5,%6,%7}, {%8,%9}, {%0,%1,%2,%3};" \
   : "+f"((c)[0]),"+f"((c)[1]),"+f"((c)[2]),"+f"((c)[3]) \
   : "r"(a0),"r"(a1),"r"(a2),"r"(a3),"r"(b0),"r"(b1))
#define F2U(x) __float_as_uint(x)

// ----------------- tensor-core 3xTF32 GEMM body (MT*64 x 64 tile, 8 warps) -------
enum { EPI_NONE=0, EPI_SCORES=1, EPI_ADDPADH=2, EPI_BIASRELU=3, EPI_QKP=4, EPI_FINAL=5 };

struct TCSmem {
    float Ah[16][136], Al[16][136];
    float Bh[16][72],  Bl[16][72];
};

template<int EPI, bool TRANSB, bool GATHER, int MT>
__device__ __forceinline__
void tcgemm_body(TCSmem& S, int bx, int by,
    const float* __restrict__ A, int lda,
    const float* __restrict__ B, int ldb,
    float* __restrict__ C, int ldc,
    int M, int Nc, int K,
    const int* __restrict__ Mdyn, const int* __restrict__ gidx,
    const float* __restrict__ ep0, const float* __restrict__ ep1,
    float scale)
{
    if (Mdyn) M = *Mdyn;
    int NB = (EPI==EPI_SCORES)? M : Nc;
    const int MROWS = MT*64;
    if (by*MROWS >= M || bx*64 >= NB) return;
    int tid=threadIdx.x, warp=tid>>5, lane=tid&31;
    int wm = (warp&3)*(MT*16), wn=(warp>>2)<<5;
    int gid=lane>>2, tg=lane&3;

    // fixed per-thread load mappings
    int rowA[MT], c4A[MT]; const float* pA[MT]; bool okA[MT];
#pragma unroll
    for (int j=0;j<MT;j++){
        int idx = tid + j*256;
        rowA[j] = idx & (MROWS-1);
        c4A[j]  = (idx/MROWS)<<2;
        int gr = by*MROWS + rowA[j];
        okA[j] = gr < M;
        int ri = okA[j]? (GATHER? gidx[gr]: gr) : 0;
        pA[j] = A + (size_t)ri*lda + c4A[j];
    }
    int rowB, c4B; const float* pB; bool okB=true;
    if (!TRANSB){
        rowB = tid>>4;               // k index within tile
        c4B  = (tid&15)<<2;          // n
        pB = B + (size_t)rowB*ldb + bx*64 + c4B;
    } else {
        rowB = tid & 63;             // n (row of B)
        c4B  = (tid>>6)<<2;          // k
        int gn = bx*64 + rowB;
        okB = gn < NB;
        pB = B + (size_t)(okB? gn:0)*ldb + c4B;
    }

    float acc[MT][4][4];
#pragma unroll
    for (int i=0;i<MT;i++)
#pragma unroll
        for (int j=0;j<4;j++)
#pragma unroll
            for (int k=0;k<4;k++) acc[i][j][k]=0.f;

    float4 aReg[MT], bReg;
#pragma unroll
    for (int j=0;j<MT;j++)
        aReg[j] = okA[j]? *(const float4*)(pA[j]) : make_float4(0.f,0.f,0.f,0.f);
    if (!TRANSB) bReg = *(const float4*)(pB);
    else         bReg = okB? *(const float4*)(pB) : make_float4(0.f,0.f,0.f,0.f);

    for (int k0=0;k0<K;k0+=16){
        // store current tile regs into split smem
#pragma unroll
        for (int j=0;j<MT;j++){
            float hx,lx;
            split_tf32(aReg[j].x,hx,lx); S.Ah[c4A[j]+0][rowA[j]]=hx; S.Al[c4A[j]+0][rowA[j]]=lx;
            split_tf32(aReg[j].y,hx,lx); S.Ah[c4A[j]+1][rowA[j]]=hx; S.Al[c4A[j]+1][rowA[j]]=lx;
            split_tf32(aReg[j].z,hx,lx); S.Ah[c4A[j]+2][rowA[j]]=hx; S.Al[c4A[j]+2][rowA[j]]=lx;
            split_tf32(aReg[j].w,hx,lx); S.Ah[c4A[j]+3][rowA[j]]=hx; S.Al[c4A[j]+3][rowA[j]]=lx;
        }
        {
            float hx,lx;
            if (!TRANSB){
                split_tf32(bReg.x,hx,lx); S.Bh[rowB][c4B+0]=hx; S.Bl[rowB][c4B+0]=lx;
                split_tf32(bReg.y,hx,lx); S.Bh[rowB][c4B+1]=hx; S.Bl[rowB][c4B+1]=lx;
                split_tf32(bReg.z,hx,lx); S.Bh[rowB][c4B+2]=hx; S.Bl[rowB][c4B+2]=lx;
                split_tf32(bReg.w,hx,lx); S.Bh[rowB][c4B+3]=hx; S.Bl[rowB][c4B+3]=lx;
            } else {
                split_tf32(bReg.x,hx,lx); S.Bh[c4B+0][rowB]=hx; S.Bl[c4B+0][rowB]=lx;
                split_tf32(bReg.y,hx,lx); S.Bh[c4B+1][rowB]=hx; S.Bl[c4B+1][rowB]=lx;
                split_tf32(bReg.z,hx,lx); S.Bh[c4B+2][rowB]=hx; S.Bl[c4B+2][rowB]=lx;
                split_tf32(bReg.w,hx,lx); S.Bh[c4B+3][rowB]=hx; S.Bl[c4B+3][rowB]=lx;
            }
        }
        __syncthreads();
        // prefetch next k tile while computing this one
        int k0p = k0 + 16;
        if (k0p < K){
#pragma unroll
            for (int j=0;j<MT;j++)
                aReg[j] = okA[j]? *(const float4*)(pA[j] + k0p) : make_float4(0.f,0.f,0.f,0.f);
            if (!TRANSB) bReg = *(const float4*)(pB + (size_t)k0p*ldb);
            else         bReg = okB? *(const float4*)(pB + k0p) : make_float4(0.f,0.f,0.f,0.f);
        }
#pragma unroll
        for (int ks=0; ks<16; ks+=8){
            unsigned ahi[MT][4], alo[MT][4], bhi[4][2], blo[4][2];
#pragma unroll
            for (int mt=0;mt<MT;mt++){
                int rb = wm + mt*16;
                ahi[mt][0]=F2U(S.Ah[ks+tg  ][rb+gid  ]); alo[mt][0]=F2U(S.Al[ks+tg  ][rb+gid  ]);
                ahi[mt][1]=F2U(S.Ah[ks+tg  ][rb+gid+8]); alo[mt][1]=F2U(S.Al[ks+tg  ][rb+gid+8]);
                ahi[mt][2]=F2U(S.Ah[ks+tg+4][rb+gid  ]); alo[mt][2]=F2U(S.Al[ks+tg+4][rb+gid  ]);
                ahi[mt][3]=F2U(S.Ah[ks+tg+4][rb+gid+8]); alo[mt][3]=F2U(S.Al[ks+tg+4][rb+gid+8]);
            }
#pragma unroll
            for (int nt=0;nt<4;nt++){
                int cb = wn + nt*8;
                bhi[nt][0]=F2U(S.Bh[ks+tg  ][cb+gid]); blo[nt][0]=F2U(S.Bl[ks+tg  ][cb+gid]);
                bhi[nt][1]=F2U(S.Bh[ks+tg+4][cb+gid]); blo[nt][1]=F2U(S.Bl[ks+tg+4][cb+gid]);
            }
#pragma unroll
            for (int mt=0;mt<MT;mt++)
#pragma unroll
                for (int nt=0;nt<4;nt++){
                    MMA_TF32(acc[mt][nt], ahi[mt][0],ahi[mt][1],ahi[mt][2],ahi[mt][3], bhi[nt][0],bhi[nt][1]);
                    MMA_TF32(acc[mt][nt], ahi[mt][0],ahi[mt][1],ahi[mt][2],ahi[mt][3], blo[nt][0],blo[nt][1]);
                    MMA_TF32(acc[mt][nt], alo[mt][0],alo[mt][1],alo[mt][2],alo[mt][3], bhi[nt][0],bhi[nt][1]);
                }
        }
        __syncthreads();
    }

    // epilogue: c0:(gid,2tg) c1:(gid,2tg+1) c2:(gid+8,2tg) c3:(gid+8,2tg+1)
#pragma unroll
    for (int mt=0;mt<MT;mt++){
#pragma unroll
        for (int nt=0;nt<4;nt++){
            int rb = by*MROWS + wm + mt*16 + gid;
            int cb = bx*64 + wn + nt*8 + (tg<<1);
#pragma unroll
            for (int e=0;e<4;e++){
                int r = rb + ((e>=2)? 8:0);
                int c = cb + (e&1);
                if (r >= M || c >= NB) continue;
                float v = acc[mt][nt][e];
                if constexpr (EPI==EPI_SCORES){
                    v *= scale;
                    if (r==c) v = NEGV;
                } else if constexpr (EPI==EPI_ADDPADH){
                    if (c < DIM) v += ep0[(size_t)r*DIM + c];
                } else if constexpr (EPI==EPI_BIASRELU){
                    v += ep0[c]; v = v>0.f ? v : 0.f;
                } else if constexpr (EPI==EPI_QKP){
                    if (c >= 256 && c < 384) v += ep0[c-256];
                } else if constexpr (EPI==EPI_FINAL){
                    float hl = ep0[(size_t)r*DIM2 + c];
                    float mm = ep1[r];
                    float mfv = (mm > 0.5f) ? 1.f : 0.f;
                    v = (1.f-mm)*hl + mm*((v+hl)*mfv);
                }
                C[(size_t)r*ldc + c] = v;
            }
        }
    }
}

template<int EPI, bool TRANSB, bool GATHER, int MT>
__global__ __launch_bounds__(256)
void tcgemm(const float* __restrict__ A, int lda,
            const float* __restrict__ B, int ldb,
            float* __restrict__ C, int ldc,
            int M, int Nc, int K,
            const int* __restrict__ Mdyn, const int* __restrict__ gidx,
            const float* __restrict__ ep0, const float* __restrict__ ep1,
            float scale)
{
    __shared__ TCSmem S;
    tcgemm_body<EPI,TRANSB,GATHER,MT>(S, blockIdx.x, blockIdx.y,
        A,lda,B,ldb,C,ldc,M,Nc,K,Mdyn,gidx,ep0,ep1,scale);
}

// ----------------- launch 0: zero agg1 / den / maxenc / ticket ---------------
__global__ void fill0_k(){
    int j = blockIdx.x*256 + threadIdx.x;      // [0,131072)
    ((float4*)g_agg1)[j] = make_float4(0.f,0.f,0.f,0.f);
    if (j < N_NODES){ g_den[j]=0.f; g_maxenc[j]=0x007FFFFFu; }
    if (j == 0) g_ticket = 0u;
}

// ----------------- launch 1: prep mega-kernel -----------------
// blocks [0,4): Wfl GEMM; [4,12): Wfh GEMM; [12,76): concat; [76,332): zero aggH
__global__ __launch_bounds__(256) void prep_k(
    const float* __restrict__ Wlout, const float* __restrict__ Wpl,
    const float* __restrict__ Whout, const float* __restrict__ Wph,
    const float* __restrict__ Wq, const float* __restrict__ Wk,
    const float* __restrict__ Wa1)
{
    __shared__ TCSmem S;
    int b = blockIdx.x;
    int tid = threadIdx.x;
    if (b < 4){
        tcgemm_body<EPI_NONE,false,false,2>(S, b, 0, Wlout,DIM2, Wpl,DIM2, g_Wfl,DIM2,
            DIM,DIM2,DIM2, nullptr,nullptr,nullptr,nullptr,0.f);
    } else if (b < 12){
        tcgemm_body<EPI_NONE,false,false,2>(S, (b-4)&3, (b-4)>>2, Whout,DIM2, Wph,DIM2, g_Wfh,DIM2,
            DIM2,DIM2,DIM2, nullptr,nullptr,nullptr,nullptr,0.f);
    } else if (b < 76){
        int i4 = (b-12)*256 + tid;             // [0,16384)
        int i = i4*4;
        int k = i>>9, c = i&511;
        float4 v;
        if (c < 128)      v = *(const float4*)(Wq  + k*128 + c);
        else if (c < 256) v = *(const float4*)(Wk  + k*128 + (c-128));
        else if (c < 384) v = *(const float4*)(Wa1 + k*128 + (c-256));
        else              v = *(const float4*)(Wa1 + (128+k)*128 + (c-384));
        ((float4*)g_Wcat)[i4] = v;
    } else {
        int j = (b-76)*256 + tid;              // [0,65536)
#pragma unroll
        for (int r=0;r<4;r++)
            ((float4*)g_aggH)[j + r*65536] = make_float4(0.f,0.f,0.f,0.f);
    }
}

// ----------------- launch 2: edge messages (gate * h[src] * shdot), atomic ------
__global__ __launch_bounds__(256) void edge1_k(
    const float* __restrict__ h, const int* __restrict__ ei,
    const float* __restrict__ esh, const float* __restrict__ ef,
    const float* __restrict__ Wlr, const float* __restrict__ wlsh)
{
    __shared__ float sW[RDIM*DIM];
    __shared__ float swsh[LDIM];
    int tid = threadIdx.x;
    for (int i=tid;i<RDIM*DIM;i+=256) sW[i]=Wlr[i];
    if (tid<LDIM) swsh[tid]=wlsh[tid];
    __syncthreads();
    int warp = tid>>5, lane = tid&31;
    int base = lane<<2;
#pragma unroll
    for (int it=0; it<4; ++it){
        int e = blockIdx.x*32 + warp*4 + it;   // 4096*32 = 131072 exact
        int src = ei[e], dst = ei[E_EDGES+e];
        float t = (lane<LDIM)? esh[(size_t)e*LDIM+lane]*swsh[lane] : 0.f;
        float shd = wredsum(t);
        float efv = (lane<RDIM)? ef[(size_t)e*RDIM+lane] : 0.f;
        float g0=0.f,g1=0.f,g2=0.f,g3=0.f;
#pragma unroll
        for (int r=0;r<RDIM;r++){
            float er = __shfl_sync(0xffffffffu, efv, r);
            g0 += er*sW[r*DIM+base+0];
            g1 += er*sW[r*DIM+base+1];
            g2 += er*sW[r*DIM+base+2];
            g3 += er*sW[r*DIM+base+3];
        }
        float4 hv = *(const float4*)(h + (size_t)src*DIM + base);
        red4(&g_agg1[(size_t)dst*DIM+base], hv.x*g0*shd, hv.y*g1*shd, hv.z*g2*shd, hv.w*g3*shd);
    }
}

// ----------------- launch 4: fused mask MLP (hidden GEMM + m + mf + scan) -------
__global__ __launch_bounds__(256) void mask_k(
    const float* __restrict__ Wms1, const float* __restrict__ bms1,
    const float* __restrict__ Wms2, const float* __restrict__ bms2)
{
    __shared__ TCSmem S;
    __shared__ int scnt[256];
    __shared__ unsigned lastFlag;
    tcgemm_body<EPI_BIASRELU,false,false,1>(S, 0, blockIdx.x, g_hloc,DIM2, Wms1,HIDD, g_hid,HIDD,
        N_NODES,HIDD,SDIM, nullptr,nullptr, bms1,nullptr,0.f);
    __syncthreads();
    int tid = threadIdx.x, warp = tid>>5, lane = tid&31;
    int r0 = blockIdx.x*64;
    float w2a = Wms2[lane], w2b = Wms2[lane+32];
    float bb = bms2[0];
#pragma unroll
    for (int i=0;i<8;i++){
        int row = r0 + warp*8 + i;
        float s = g_hid[row*HIDD+lane]*w2a + g_hid[row*HIDD+lane+32]*w2b;
        s = wredsum(s);
        if (lane==0){
            float mm = 1.f/(1.f+expf(-(s+bb)));
            g_m[row] = mm;
            g_mf[row] = (mm > 0.5f) ? 1 : 0;
        }
    }
    __syncthreads();
    if (tid==0){
        __threadfence();
        lastFlag = (atomicAdd(&g_ticket, 1u) == 63u);
    }
    __syncthreads();
    if (lastFlag){
        int base = tid*16;
        int loc[16]; int c=0;
#pragma unroll
        for (int j=0;j<16;j++){
            loc[j] = *((volatile int*)&g_mf[base+j]);
            c += loc[j];
        }
        scnt[tid]=c; __syncthreads();
        for (int off=1; off<256; off<<=1){
            int v = scnt[tid];
            int a = (tid>=off)? scnt[tid-off] : 0;
            __syncthreads();
            scnt[tid] = v+a;
            __syncthreads();
        }
        int pos = scnt[tid]-c;
#pragma unroll
        for (int j=0;j<16;j++)
            if (loc[j]) g_vlist[pos++] = base+j;
        if (tid==255) g_Nv = scnt[255];
    }
}

// ----------------- launch 7: per-row top-16 (tie -> lowest index) ---------------
__global__ __launch_bounds__(128) void topk_k()
{
    int Nv = g_Nv;
    int vi = blockIdx.x;
    if (vi >= Nv) return;
    __shared__ float vals[N_NODES];
    __shared__ float rv[128];
    __shared__ int   ri[128];
    int tid = threadIdx.x;
    const float* row = &g_S[(size_t)vi*N_NODES];
    for (int j=tid;j<Nv;j+=128) vals[j]=row[j];
    __syncthreads();
    for (int t=0;t<TOPKK;t++){
        float bv=-3.4e38f; int bi=0x7fffffff;
        for (int j=tid;j<Nv;j+=128){
            float v=vals[j];
            if (v>bv || (v==bv && j<bi)){bv=v;bi=j;}
        }
        rv[tid]=bv; ri[tid]=bi;
        __syncthreads();
        for (int off=64;off>0;off>>=1){
            if (tid<off){
                float ov=rv[tid+off]; int oi=ri[tid+off];
                if (ov>rv[tid] || (ov==rv[tid] && oi<ri[tid])){rv[tid]=ov;ri[tid]=oi;}
            }
            __syncthreads();
        }
        if (tid==0){
            int bj = ri[0];
            if (rv[0] > NEGV*0.5f){
                g_vdc[vi*TOPKK+t]=bj;
                g_vdo[vi*TOPKK+t]=g_vlist[bj];
            } else {
                g_vdc[vi*TOPKK+t]=-1;
                g_vdo[vi*TOPKK+t]=-1;
            }
            vals[bj] = -3.4e38f;
        }
        __syncthreads();
    }
}

// ----------------- launch 8: virtual edge MLP score ---------------
__global__ __launch_bounds__(256) void vedge_mlp(
    const float* __restrict__ pos, const float* __restrict__ Wa1,
    const float* __restrict__ Wa2, const float* __restrict__ ba2,
    const float* __restrict__ whsh)
{
    __shared__ float sW1[RDIM*SDIM];
    __shared__ float sW2[SDIM];
    int tid=threadIdx.x;
    for (int i=tid;i<RDIM*SDIM;i+=256) sW1[i]=Wa1[2*SDIM*SDIM + i];
    for (int i=tid;i<SDIM;i+=256) sW2[i]=Wa2[i];
    __syncthreads();
    int Nv = g_Nv;
    int warp = tid>>5, lane = tid&31;
#pragma unroll
    for (int it=0; it<4; ++it){
        int s = blockIdx.x*32 + warp*4 + it;
        if (s >= Nv*TOPKK) break;
        int jo = g_vdo[s];
        if (jo < 0) continue;
        int vi = s >> 4;
        int jc = g_vdc[s];
        int i  = g_vlist[vi];
        float dx = pos[i*3+0]-pos[jo*3+0];
        float dy = pos[i*3+1]-pos[jo*3+1];
        float dz = pos[i*3+2]-pos[jo*3+2];
        float r = sqrtf(dx*dx+dy*dy+dz*dz);
        float rf[8];
#pragma unroll
        for (int k=0;k<8;k++){ float cc=k*(5.0f/7.0f); float d=r-cc; rf[k]=expf(-4.0f*d*d); }
        if (lane < 8) g_rf[s*RDIM+lane] = rf[lane];
        if (lane==0) g_shd[s] = sh_dot(dx,dy,dz, whsh);
        float sum = 0.f;
#pragma unroll
        for (int u=0;u<4;u++){
            int d = lane + u*32;
            float hv = g_qkp[(size_t)vi*512 + 256 + d] + g_qkp[(size_t)jc*512 + 384 + d];
#pragma unroll
            for (int k=0;k<8;k++) hv += rf[k]*sW1[k*SDIM+d];
            hv = hv>0.f ? hv : 0.f;
            sum += hv*sW2[d];
        }
        sum = wredsum(sum);
        if (lane==0){
            float sc = sum + ba2[0];
            g_sc[s] = sc;
            atomicMax(&g_maxenc[jo], enc(sc));
        }
    }
}

// ----------------- launch 9: softmax denominator ---------------
__global__ void softmax2()
{
    int s = blockIdx.x*blockDim.x + threadIdx.x;
    int Nv = g_Nv;
    if (s >= Nv*TOPKK) return;
    int jo = g_vdo[s];
    if (jo < 0) return;
    float mx = dec(g_maxenc[jo]);
    float e = expf(g_sc[s]-mx);
    g_ex[s] = e;
    atomicAdd(&g_den[jo], e);
}

// ----------------- launch 10: hierarchical messages (real + virtual fused) ------
// blocks [0,4096): real edges (32/block); [4096,6144): virtual edges (32/block)
__global__ __launch_bounds__(256) void msgsH_k(
    const float* __restrict__ pos, const int* __restrict__ ei,
    const float* __restrict__ Whr, const float* __restrict__ whsh)
{
    __shared__ float sW[RDIM*DIM2];
    __shared__ float swsh[LDIM];
    int tid=threadIdx.x;
    for (int i=tid;i<RDIM*DIM2;i+=256) sW[i]=Whr[i];
    if (tid<LDIM) swsh[tid]=whsh[tid];
    __syncthreads();
    int warp = tid>>5, lane = tid&31;
    int base = lane*8;
    int b = blockIdx.x;
    if (b < 4096){
#pragma unroll
        for (int it=0; it<4; ++it){
            int e = b*32 + warp*4 + it;
            int src = ei[e], dst = ei[E_EDGES+e];
            if (!(g_mf[src] & g_mf[dst])) continue;
            float dx = pos[src*3+0]-pos[dst*3+0];
            float dy = pos[src*3+1]-pos[dst*3+1];
            float dz = pos[src*3+2]-pos[dst*3+2];
            float r = sqrtf(dx*dx+dy*dy+dz*dz);
            float shd = sh_dot(dx,dy,dz, swsh);
            float rf[8];
#pragma unroll
            for (int k=0;k<8;k++){ float cc=k*(5.0f/7.0f); float d=r-cc; rf[k]=expf(-4.0f*d*d); }
            float g[8];
#pragma unroll
            for (int u=0;u<8;u++){
                float acc=0.f;
#pragma unroll
                for (int k=0;k<8;k++) acc += rf[k]*sW[k*DIM2+base+u];
                g[u]=acc;
            }
            float4 h0 = *(const float4*)&g_hloc[(size_t)src*DIM2+base];
            float4 h1 = *(const float4*)&g_hloc[(size_t)src*DIM2+base+4];
            red4(&g_aggH[(size_t)dst*DIM2+base  ], h0.x*g[0]*shd, h0.y*g[1]*shd, h0.z*g[2]*shd, h0.w*g[3]*shd);
            red4(&g_aggH[(size_t)dst*DIM2+base+4], h1.x*g[4]*shd, h1.y*g[5]*shd, h1.z*g[6]*shd, h1.w*g[7]*shd);
        }
    } else {
        int Nv = g_Nv;
#pragma unroll
        for (int it=0; it<4; ++it){
            int s = (b-4096)*32 + warp*4 + it;
            if (s >= Nv*TOPKK) break;
            int jo = g_vdo[s];
            if (jo < 0) continue;
            int vi = s >> 4;
            int i  = g_vlist[vi];
            float wv = g_ex[s]/(g_den[jo]+1e-12f);
            float shd = g_shd[s];
            float rf[8];
#pragma unroll
            for (int k=0;k<8;k++) rf[k]=g_rf[s*RDIM+k]*wv;
            float g[8];
#pragma unroll
            for (int u=0;u<8;u++){
                float acc=0.f;
#pragma unroll
                for (int k=0;k<8;k++) acc += rf[k]*sW[k*DIM2+base+u];
                g[u]=acc;
            }
            float4 h0 = *(const float4*)&g_hloc[(size_t)i*DIM2+base];
            float4 h1 = *(const float4*)&g_hloc[(size_t)i*DIM2+base+4];
            red4(&g_aggH[(size_t)jo*DIM2+base  ], h0.x*g[0]*shd, h0.y*g[1]*shd, h0.z*g[2]*shd, h0.w*g[3]*shd);
            red4(&g_aggH[(size_t)jo*DIM2+base+4], h1.x*g[4]*shd, h1.y*g[5]*shd, h1.z*g[6]*shd, h1.w*g[7]*shd);
        }
    }
}

// ----------------- launcher ---------------
extern "C" void kernel_launch(void* const* d_in, const int* in_sizes, int n_in,
                              void* d_out, int out_size)
{
    const float* h    = (const float*)d_in[0];
    const float* pos  = (const float*)d_in[1];
    const int*   ei   = (const int*)  d_in[2];
    const float* esh  = (const float*)d_in[3];
    const float* ef   = (const float*)d_in[4];
    const float* Wlr  = (const float*)d_in[6];
    const float* wlsh = (const float*)d_in[7];
    const float* Wlout= (const float*)d_in[8];
    const float* Wpl  = (const float*)d_in[9];
    const float* Wms1 = (const float*)d_in[10];
    const float* bms1 = (const float*)d_in[11];
    const float* Wms2 = (const float*)d_in[12];
    const float* bms2 = (const float*)d_in[13];
    const float* Wq   = (const float*)d_in[14];
    const float* Wk   = (const float*)d_in[15];
    const float* Wa1  = (const float*)d_in[16];
    const float* ba1  = (const float*)d_in[17];
    const float* Wa2  = (const float*)d_in[18];
    const float* ba2  = (const float*)d_in[19];
    const float* Whr  = (const float*)d_in[20];
    const float* whsh = (const float*)d_in[21];
    const float* Whout= (const float*)d_in[22];
    const float* Wph  = (const float*)d_in[23];
    float* out = (float*)d_out;

    float *p_agg1,*p_hloc,*p_qkp,*p_S,*p_aggH,*p_m,*p_Wfl,*p_Wfh,*p_Wcat;
    int *p_Nv,*p_vlist;
    cudaGetSymbolAddress((void**)&p_agg1, g_agg1);
    cudaGetSymbolAddress((void**)&p_hloc, g_hloc);
    cudaGetSymbolAddress((void**)&p_qkp , g_qkp );
    cudaGetSymbolAddress((void**)&p_S   , g_S   );
    cudaGetSymbolAddress((void**)&p_aggH, g_aggH);
    cudaGetSymbolAddress((void**)&p_m   , g_m   );
    cudaGetSymbolAddress((void**)&p_Wfl , g_Wfl );
    cudaGetSymbolAddress((void**)&p_Wfh , g_Wfh );
    cudaGetSymbolAddress((void**)&p_Wcat, g_Wcat);
    cudaGetSymbolAddress((void**)&p_Nv  , g_Nv  );
    cudaGetSymbolAddress((void**)&p_vlist, g_vlist);

    const float scal = 0.088388347648318447f; // 1/sqrt(128)

    fill0_k<<<512,256>>>();
    prep_k<<<332,256>>>(Wlout,Wpl,Whout,Wph,Wq,Wk,Wa1);
    edge1_k<<<4096,256>>>(h,ei,esh,ef,Wlr,wlsh);
    // h_local = agg1 @ Wfl + pad(h)
    tcgemm<EPI_ADDPADH,false,false,1><<<dim3(4,64),256>>>(p_agg1,DIM, p_Wfl,DIM2, p_hloc,DIM2,
        N_NODES,DIM2,DIM, nullptr,nullptr, h,nullptr,0.f);
    // hidden GEMM + m + mf + valid-node scan (last block)
    mask_k<<<64,256>>>(Wms1,bms1,Wms2,bms2);
    // fused gathered GEMM: [q | k | P1(+bias) | P2] = hloc_valid @ Wcat
    tcgemm<EPI_QKP,false,true,1><<<dim3(8,64),256>>>(p_hloc,DIM2, p_Wcat,512, p_qkp,512,
        N_NODES,512,SDIM, p_Nv, p_vlist, ba1,nullptr,0.f);
    // scores = q @ k^T * scale, diag=NEG (compact Nv x Nv)
    tcgemm<EPI_SCORES,true,false,2><<<dim3(64,32),256>>>(p_qkp,512, p_qkp+SDIM,512, p_S,N_NODES,
        N_NODES,N_NODES,SDIM, p_Nv, nullptr, nullptr,nullptr, scal);
    topk_k<<<N_NODES,128>>>();
    vedge_mlp<<<N_NODES*TOPKK/32,256>>>(pos, Wa1, Wa2, ba2, whsh);
    softmax2<<<N_NODES*TOPKK/256,256>>>();
    msgsH_k<<<6144,256>>>(pos,ei,Whr,whsh);
    // out = (1-m)*h_local + m*((aggH@Wfh + h_local)*mf)
    tcgemm<EPI_FINAL,false,false,1><<<dim3(4,64),256>>>(p_aggH,DIM2, p_Wfh,DIM2, out,DIM2,
        N_NODES,DIM2,DIM2, nullptr,nullptr, p_hloc, p_m, 0.f);
}

// round 16
// speedup vs baseline: 1.4027x; 1.0871x over previous
#include <cuda_runtime.h>
#include <cuda_bf16.h>
#include <math.h>

#define N_NODES 4096
#define E_EDGES 131072
#define DIM     128
#define DIM2    256
#define SDIM    128
#define RDIM    8
#define LDIM    16
#define HIDD    64
#define TOPKK   16
#define NEGV    (-1000000000.0f)

// ----------------- scratch (device globals; no allocation) ---------------
__device__ float    g_agg1[N_NODES*DIM];
__device__ float    g_hloc[N_NODES*DIM2];
__device__ float    g_hid [N_NODES*HIDD];
__device__ float    g_m   [N_NODES];
__device__ int      g_mf  [N_NODES];
__device__ int      g_vlist[N_NODES];
__device__ int      g_Nv;
__device__ unsigned g_ticket;
__device__ float    g_qkp[N_NODES*512];     // [q | k | P1 | P2] per valid row
__device__ float    g_S [N_NODES*N_NODES];
__device__ int      g_vdc[N_NODES*TOPKK];
__device__ int      g_vdo[N_NODES*TOPKK];
__device__ float    g_sc [N_NODES*TOPKK];
__device__ float    g_ex [N_NODES*TOPKK];
__device__ float    g_shd[N_NODES*TOPKK];
__device__ float    g_rf [N_NODES*TOPKK*RDIM];
__device__ unsigned g_maxenc[N_NODES];
__device__ float    g_den[N_NODES];
__device__ float    g_aggH[N_NODES*DIM2];
__device__ float    g_Wfl[DIM*DIM2];        // W_loc_out @ W_prod_loc
__device__ float    g_Wfh[DIM2*DIM2];       // W_h_out @ W_prod_h
__device__ float    g_Wcat[DIM*512];        // [Wq | Wk | Wa1[0:128] | Wa1[128:256]]

// ----------------- helpers ---------------
__device__ __forceinline__ float wredsum(float v){
#pragma unroll
    for (int o=16;o>0;o>>=1) v += __shfl_xor_sync(0xffffffffu, v, o);
    return v;
}
__device__ __forceinline__ unsigned enc(float f){
    unsigned u=__float_as_uint(f);
    return (u&0x80000000u)? ~u : (u|0x80000000u);
}
__device__ __forceinline__ float dec(unsigned u){
    return (u&0x80000000u)? __uint_as_float(u & 0x7fffffffu) : __uint_as_float(~u);
}
__device__ __forceinline__ void red4(float* a, float x,float y,float z,float w){
    asm volatile("red.global.add.v4.f32 [%0], {%1,%2,%3,%4};"
                 :: "l"(a),"f"(x),"f"(y),"f"(z),"f"(w) : "memory");
}
__device__ __forceinline__ float sh_dot(float vx,float vy,float vz, const float* w){
    float n = sqrtf(vx*vx+vy*vy+vz*vz);
    float inv = 1.0f/(n+1e-9f);
    float x=vx*inv, y=vy*inv, z=vz*inv;
    return w[0]+w[1]*x+w[2]*y+w[3]*z
      + w[4]*x*x + w[5]*y*y + w[6]*z*z
      + w[7]*x*y + w[8]*x*z + w[9]*y*z
      + w[10]*x*x*x + w[11]*y*y*y + w[12]*z*z*z
      + w[13]*x*x*y + w[14]*y*y*z + w[15]*z*z*x;
}
__device__ __forceinline__ void split_tf32(float f, float& hi, float& lo){
    unsigned h; asm("cvt.rna.tf32.f32 %0, %1;" : "=r"(h) : "f"(f));
    float l = f - __uint_as_float(h);
    unsigned lu; asm("cvt.rna.tf32.f32 %0, %1;" : "=r"(lu) : "f"(l));
    hi = __uint_as_float(h); lo = __uint_as_float(lu);
}
#define MMA_TF32(c, a0,a1,a2,a3, b0,b1) \
  asm volatile("mma.sync.aligned.m16n8k8.row.col.f32.tf32.tf32.f32 " \
   "{%0,%1,%2,%3}, {%4,%5,%6,%7}, {%8,%9}, {%0,%1,%2,%3};" \
   : "+f"((c)[0]),"+f"((c)[1]),"+f"((c)[2]),"+f"((c)[3]) \
   : "r"(a0),"r"(a1),"r"(a2),"r"(a3),"r"(b0),"r"(b1))
#define F2U(x) __float_as_uint(x)

// ----------------- tensor-core 3xTF32 GEMM body (MT*64 x 64 tile, 8 warps) -------
// Double-buffered smem: one __syncthreads per k-tile.
enum { EPI_NONE=0, EPI_SCORES=1, EPI_ADDPADH=2, EPI_BIASRELU=3, EPI_QKP=4, EPI_FINAL=5 };

struct TCSmem {
    float Ah[16][136], Al[16][136];
    float Bh[16][72],  Bl[16][72];
};

template<int EPI, bool TRANSB, bool GATHER, int MT>
__device__ __forceinline__
void tcgemm_body(TCSmem* S2, int bx, int by,
    const float* __restrict__ A, int lda,
    const float* __restrict__ B, int ldb,
    float* __restrict__ C, int ldc,
    int M, int Nc, int K,
    const int* __restrict__ Mdyn, const int* __restrict__ gidx,
    const float* __restrict__ ep0, const float* __restrict__ ep1,
    float scale)
{
    if (Mdyn) M = *Mdyn;
    int NB = (EPI==EPI_SCORES)? M : Nc;
    const int MROWS = MT*64;
    if (by*MROWS >= M || bx*64 >= NB) return;
    int tid=threadIdx.x, warp=tid>>5, lane=tid&31;
    int wm = (warp&3)*(MT*16), wn=(warp>>2)<<5;
    int gid=lane>>2, tg=lane&3;

    // fixed per-thread load mappings
    int rowA[MT], c4A[MT]; const float* pA[MT]; bool okA[MT];
#pragma unroll
    for (int j=0;j<MT;j++){
        int idx = tid + j*256;
        rowA[j] = idx & (MROWS-1);
        c4A[j]  = (idx/MROWS)<<2;
        int gr = by*MROWS + rowA[j];
        okA[j] = gr < M;
        int ri = okA[j]? (GATHER? gidx[gr]: gr) : 0;
        pA[j] = A + (size_t)ri*lda + c4A[j];
    }
    int rowB, c4B; const float* pB; bool okB=true;
    if (!TRANSB){
        rowB = tid>>4;               // k index within tile
        c4B  = (tid&15)<<2;          // n
        pB = B + (size_t)rowB*ldb + bx*64 + c4B;
    } else {
        rowB = tid & 63;             // n (row of B)
        c4B  = (tid>>6)<<2;          // k
        int gn = bx*64 + rowB;
        okB = gn < NB;
        pB = B + (size_t)(okB? gn:0)*ldb + c4B;
    }

    float acc[MT][4][4];
#pragma unroll
    for (int i=0;i<MT;i++)
#pragma unroll
        for (int j=0;j<4;j++)
#pragma unroll
            for (int k=0;k<4;k++) acc[i][j][k]=0.f;

    float4 aReg[MT], bReg;
#pragma unroll
    for (int j=0;j<MT;j++)
        aReg[j] = okA[j]? *(const float4*)(pA[j]) : make_float4(0.f,0.f,0.f,0.f);
    if (!TRANSB) bReg = *(const float4*)(pB);
    else         bReg = okB? *(const float4*)(pB) : make_float4(0.f,0.f,0.f,0.f);

    int stage = 0;
    for (int k0=0;k0<K;k0+=16){
        TCSmem& S = S2[stage];
        // store current tile regs into split smem (opposite buffer from last compute)
#pragma unroll
        for (int j=0;j<MT;j++){
            float hx,lx;
            split_tf32(aReg[j].x,hx,lx); S.Ah[c4A[j]+0][rowA[j]]=hx; S.Al[c4A[j]+0][rowA[j]]=lx;
            split_tf32(aReg[j].y,hx,lx); S.Ah[c4A[j]+1][rowA[j]]=hx; S.Al[c4A[j]+1][rowA[j]]=lx;
            split_tf32(aReg[j].z,hx,lx); S.Ah[c4A[j]+2][rowA[j]]=hx; S.Al[c4A[j]+2][rowA[j]]=lx;
            split_tf32(aReg[j].w,hx,lx); S.Ah[c4A[j]+3][rowA[j]]=hx; S.Al[c4A[j]+3][rowA[j]]=lx;
        }
        {
            float hx,lx;
            if (!TRANSB){
                split_tf32(bReg.x,hx,lx); S.Bh[rowB][c4B+0]=hx; S.Bl[rowB][c4B+0]=lx;
                split_tf32(bReg.y,hx,lx); S.Bh[rowB][c4B+1]=hx; S.Bl[rowB][c4B+1]=lx;
                split_tf32(bReg.z,hx,lx); S.Bh[rowB][c4B+2]=hx; S.Bl[rowB][c4B+2]=lx;
                split_tf32(bReg.w,hx,lx); S.Bh[rowB][c4B+3]=hx; S.Bl[rowB][c4B+3]=lx;
            } else {
                split_tf32(bReg.x,hx,lx); S.Bh[c4B+0][rowB]=hx; S.Bl[c4B+0][rowB]=lx;
                split_tf32(bReg.y,hx,lx); S.Bh[c4B+1][rowB]=hx; S.Bl[c4B+1][rowB]=lx;
                split_tf32(bReg.z,hx,lx); S.Bh[c4B+2][rowB]=hx; S.Bl[c4B+2][rowB]=lx;
                split_tf32(bReg.w,hx,lx); S.Bh[c4B+3][rowB]=hx; S.Bl[c4B+3][rowB]=lx;
            }
        }
        __syncthreads();
        // prefetch next k tile into registers while computing this one
        int k0p = k0 + 16;
        if (k0p < K){
#pragma unroll
            for (int j=0;j<MT;j++)
                aReg[j] = okA[j]? *(const float4*)(pA[j] + k0p) : make_float4(0.f,0.f,0.f,0.f);
            if (!TRANSB) bReg = *(const float4*)(pB + (size_t)k0p*ldb);
            else         bReg = okB? *(const float4*)(pB + k0p) : make_float4(0.f,0.f,0.f,0.f);
        }
#pragma unroll
        for (int ks=0; ks<16; ks+=8){
            unsigned ahi[MT][4], alo[MT][4], bhi[4][2], blo[4][2];
#pragma unroll
            for (int mt=0;mt<MT;mt++){
                int rb = wm + mt*16;
                ahi[mt][0]=F2U(S.Ah[ks+tg  ][rb+gid  ]); alo[mt][0]=F2U(S.Al[ks+tg  ][rb+gid  ]);
                ahi[mt][1]=F2U(S.Ah[ks+tg  ][rb+gid+8]); alo[mt][1]=F2U(S.Al[ks+tg  ][rb+gid+8]);
                ahi[mt][2]=F2U(S.Ah[ks+tg+4][rb+gid  ]); alo[mt][2]=F2U(S.Al[ks+tg+4][rb+gid  ]);
                ahi[mt][3]=F2U(S.Ah[ks+tg+4][rb+gid+8]); alo[mt][3]=F2U(S.Al[ks+tg+4][rb+gid+8]);
            }
#pragma unroll
            for (int nt=0;nt<4;nt++){
                int cb = wn + nt*8;
                bhi[nt][0]=F2U(S.Bh[ks+tg  ][cb+gid]); blo[nt][0]=F2U(S.Bl[ks+tg  ][cb+gid]);
                bhi[nt][1]=F2U(S.Bh[ks+tg+4][cb+gid]); blo[nt][1]=F2U(S.Bl[ks+tg+4][cb+gid]);
            }
#pragma unroll
            for (int mt=0;mt<MT;mt++)
#pragma unroll
                for (int nt=0;nt<4;nt++){
                    MMA_TF32(acc[mt][nt], ahi[mt][0],ahi[mt][1],ahi[mt][2],ahi[mt][3], bhi[nt][0],bhi[nt][1]);
                    MMA_TF32(acc[mt][nt], ahi[mt][0],ahi[mt][1],ahi[mt][2],ahi[mt][3], blo[nt][0],blo[nt][1]);
                    MMA_TF32(acc[mt][nt], alo[mt][0],alo[mt][1],alo[mt][2],alo[mt][3], bhi[nt][0],bhi[nt][1]);
                }
        }
        stage ^= 1;
    }

    // epilogue: c0:(gid,2tg) c1:(gid,2tg+1) c2:(gid+8,2tg) c3:(gid+8,2tg+1)
#pragma unroll
    for (int mt=0;mt<MT;mt++){
#pragma unroll
        for (int nt=0;nt<4;nt++){
            int rb = by*MROWS + wm + mt*16 + gid;
            int cb = bx*64 + wn + nt*8 + (tg<<1);
#pragma unroll
            for (int e=0;e<4;e++){
                int r = rb + ((e>=2)? 8:0);
                int c = cb + (e&1);
                if (r >= M || c >= NB) continue;
                float v = acc[mt][nt][e];
                if constexpr (EPI==EPI_SCORES){
                    v *= scale;
                    if (r==c) v = NEGV;
                } else if constexpr (EPI==EPI_ADDPADH){
                    if (c < DIM) v += ep0[(size_t)r*DIM + c];
                } else if constexpr (EPI==EPI_BIASRELU){
                    v += ep0[c]; v = v>0.f ? v : 0.f;
                } else if constexpr (EPI==EPI_QKP){
                    if (c >= 256 && c < 384) v += ep0[c-256];
                } else if constexpr (EPI==EPI_FINAL){
                    float hl = ep0[(size_t)r*DIM2 + c];
                    float mm = ep1[r];
                    float mfv = (mm > 0.5f) ? 1.f : 0.f;
                    v = (1.f-mm)*hl + mm*((v+hl)*mfv);
                }
                C[(size_t)r*ldc + c] = v;
            }
        }
    }
}

template<int EPI, bool TRANSB, bool GATHER, int MT>
__global__ __launch_bounds__(256)
void tcgemm(const float* __restrict__ A, int lda,
            const float* __restrict__ B, int ldb,
            float* __restrict__ C, int ldc,
            int M, int Nc, int K,
            const int* __restrict__ Mdyn, const int* __restrict__ gidx,
            const float* __restrict__ ep0, const float* __restrict__ ep1,
            float scale)
{
    extern __shared__ char smemraw[];
    tcgemm_body<EPI,TRANSB,GATHER,MT>((TCSmem*)smemraw, blockIdx.x, blockIdx.y,
        A,lda,B,ldb,C,ldc,M,Nc,K,Mdyn,gidx,ep0,ep1,scale);
}

// ----------------- launch 0: prep mega-kernel (+ all zero/reset work) -----------
// blocks [0,4): Wfl GEMM; [4,12): Wfh GEMM; [12,76): concat; [76,332): zero aggH;
// [332,844): zero agg1 + den/maxenc/ticket reset
__global__ __launch_bounds__(256) void prep_k(
    const float* __restrict__ Wlout, const float* __restrict__ Wpl,
    const float* __restrict__ Whout, const float* __restrict__ Wph,
    const float* __restrict__ Wq, const float* __restrict__ Wk,
    const float* __restrict__ Wa1)
{
    extern __shared__ char smemraw[];
    int b = blockIdx.x;
    int tid = threadIdx.x;
    if (b < 4){
        tcgemm_body<EPI_NONE,false,false,2>((TCSmem*)smemraw, b, 0, Wlout,DIM2, Wpl,DIM2, g_Wfl,DIM2,
            DIM,DIM2,DIM2, nullptr,nullptr,nullptr,nullptr,0.f);
    } else if (b < 12){
        tcgemm_body<EPI_NONE,false,false,2>((TCSmem*)smemraw, (b-4)&3, (b-4)>>2, Whout,DIM2, Wph,DIM2, g_Wfh,DIM2,
            DIM2,DIM2,DIM2, nullptr,nullptr,nullptr,nullptr,0.f);
    } else if (b < 76){
        int i4 = (b-12)*256 + tid;             // [0,16384)
        int i = i4*4;
        int k = i>>9, c = i&511;
        float4 v;
        if (c < 128)      v = *(const float4*)(Wq  + k*128 + c);
        else if (c < 256) v = *(const float4*)(Wk  + k*128 + (c-128));
        else if (c < 384) v = *(const float4*)(Wa1 + k*128 + (c-256));
        else              v = *(const float4*)(Wa1 + (128+k)*128 + (c-384));
        ((float4*)g_Wcat)[i4] = v;
    } else if (b < 332){
        int j = (b-76)*256 + tid;              // [0,65536)
#pragma unroll
        for (int r=0;r<4;r++)
            ((float4*)g_aggH)[j + r*65536] = make_float4(0.f,0.f,0.f,0.f);
    } else {
        int j = (b-332)*256 + tid;             // [0,131072)
        ((float4*)g_agg1)[j] = make_float4(0.f,0.f,0.f,0.f);
        if (j < N_NODES){ g_den[j]=0.f; g_maxenc[j]=0x007FFFFFu; }
        if (j == 0) g_ticket = 0u;
    }
}

// ----------------- launch 1: edge messages (gate * h[src] * shdot), atomic ------
__global__ __launch_bounds__(256) void edge1_k(
    const float* __restrict__ h, const int* __restrict__ ei,
    const float* __restrict__ esh, const float* __restrict__ ef,
    const float* __restrict__ Wlr, const float* __restrict__ wlsh)
{
    __shared__ float sW[RDIM*DIM];
    __shared__ float swsh[LDIM];
    int tid = threadIdx.x;
    for (int i=tid;i<RDIM*DIM;i+=256) sW[i]=Wlr[i];
    if (tid<LDIM) swsh[tid]=wlsh[tid];
    __syncthreads();
    int warp = tid>>5, lane = tid&31;
    int base = lane<<2;
#pragma unroll
    for (int it=0; it<4; ++it){
        int e = blockIdx.x*32 + warp*4 + it;   // 4096*32 = 131072 exact
        int src = ei[e], dst = ei[E_EDGES+e];
        float t = (lane<LDIM)? esh[(size_t)e*LDIM+lane]*swsh[lane] : 0.f;
        float shd = wredsum(t);
        float efv = (lane<RDIM)? ef[(size_t)e*RDIM+lane] : 0.f;
        float g0=0.f,g1=0.f,g2=0.f,g3=0.f;
#pragma unroll
        for (int r=0;r<RDIM;r++){
            float er = __shfl_sync(0xffffffffu, efv, r);
            g0 += er*sW[r*DIM+base+0];
            g1 += er*sW[r*DIM+base+1];
            g2 += er*sW[r*DIM+base+2];
            g3 += er*sW[r*DIM+base+3];
        }
        float4 hv = *(const float4*)(h + (size_t)src*DIM + base);
        red4(&g_agg1[(size_t)dst*DIM+base], hv.x*g0*shd, hv.y*g1*shd, hv.z*g2*shd, hv.w*g3*shd);
    }
}

// ----------------- launch 3: fused mask MLP (hidden GEMM + m + mf + scan) -------
__global__ __launch_bounds__(256) void mask_k(
    const float* __restrict__ Wms1, const float* __restrict__ bms1,
    const float* __restrict__ Wms2, const float* __restrict__ bms2)
{
    extern __shared__ char smemraw[];
    __shared__ int scnt[256];
    __shared__ unsigned lastFlag;
    tcgemm_body<EPI_BIASRELU,false,false,1>((TCSmem*)smemraw, 0, blockIdx.x, g_hloc,DIM2, Wms1,HIDD, g_hid,HIDD,
        N_NODES,HIDD,SDIM, nullptr,nullptr, bms1,nullptr,0.f);
    __syncthreads();
    int tid = threadIdx.x, warp = tid>>5, lane = tid&31;
    int r0 = blockIdx.x*64;
    float w2a = Wms2[lane], w2b = Wms2[lane+32];
    float bb = bms2[0];
#pragma unroll
    for (int i=0;i<8;i++){
        int row = r0 + warp*8 + i;
        float s = g_hid[row*HIDD+lane]*w2a + g_hid[row*HIDD+lane+32]*w2b;
        s = wredsum(s);
        if (lane==0){
            float mm = 1.f/(1.f+expf(-(s+bb)));
            g_m[row] = mm;
            g_mf[row] = (mm > 0.5f) ? 1 : 0;
        }
    }
    __syncthreads();
    if (tid==0){
        __threadfence();
        lastFlag = (atomicAdd(&g_ticket, 1u) == 63u);
    }
    __syncthreads();
    if (lastFlag){
        int base = tid*16;
        int loc[16]; int c=0;
#pragma unroll
        for (int j=0;j<16;j++){
            loc[j] = *((volatile int*)&g_mf[base+j]);
            c += loc[j];
        }
        scnt[tid]=c; __syncthreads();
        for (int off=1; off<256; off<<=1){
            int v = scnt[tid];
            int a = (tid>=off)? scnt[tid-off] : 0;
            __syncthreads();
            scnt[tid] = v+a;
            __syncthreads();
        }
        int pos = scnt[tid]-c;
#pragma unroll
        for (int j=0;j<16;j++)
            if (loc[j]) g_vlist[pos++] = base+j;
        if (tid==255) g_Nv = scnt[255];
    }
}

// ----------------- launch 6: per-row top-16 (tie -> lowest index) ---------------
// float4 scan + warp shfl reduce; 2 syncthreads per pass.
__global__ __launch_bounds__(128) void topk_k()
{
    int Nv = g_Nv;
    int vi = blockIdx.x;
    if (vi >= Nv) return;
    __shared__ float vals[N_NODES];
    __shared__ float wv_[4];
    __shared__ int   wi_[4];
    int tid = threadIdx.x, warp = tid>>5, lane = tid&31;
    const float* row = &g_S[(size_t)vi*N_NODES];
    for (int j=tid;j<Nv;j+=128) vals[j]=row[j];
    __syncthreads();
    int Nv4 = Nv & ~3;
    for (int t=0;t<TOPKK;t++){
        float bv=-3.4e38f; int bi=0x7fffffff;
        for (int jb=tid*4; jb<Nv4; jb+=512){
            float4 v = *(const float4*)&vals[jb];
            if (v.x>bv){bv=v.x;bi=jb;}
            if (v.y>bv){bv=v.y;bi=jb+1;}
            if (v.z>bv){bv=v.z;bi=jb+2;}
            if (v.w>bv){bv=v.w;bi=jb+3;}
        }
        {   // tail (Nv not multiple of 4)
            int j = Nv4 + tid;
            if (j < Nv){
                float v = vals[j];
                if (v>bv || (v==bv && j<bi)){bv=v;bi=j;}
            }
        }
#pragma unroll
        for (int o=16;o>0;o>>=1){
            float ov = __shfl_xor_sync(0xffffffffu,bv,o);
            int   oi = __shfl_xor_sync(0xffffffffu,bi,o);
            if (ov>bv || (ov==bv && oi<bi)){bv=ov;bi=oi;}
        }
        if (lane==0){ wv_[warp]=bv; wi_[warp]=bi; }
        __syncthreads();
        if (tid==0){
#pragma unroll
            for (int w=1;w<4;w++){
                if (wv_[w]>bv || (wv_[w]==bv && wi_[w]<bi)){bv=wv_[w];bi=wi_[w];}
            }
            if (bv > NEGV*0.5f){
                g_vdc[vi*TOPKK+t]=bi;
                g_vdo[vi*TOPKK+t]=g_vlist[bi];
            } else {
                g_vdc[vi*TOPKK+t]=-1;
                g_vdo[vi*TOPKK+t]=-1;
            }
            vals[bi] = -3.4e38f;
        }
        __syncthreads();
    }
}

// ----------------- launch 7: virtual edge MLP score ---------------
__global__ __launch_bounds__(256) void vedge_mlp(
    const float* __restrict__ pos, const float* __restrict__ Wa1,
    const float* __restrict__ Wa2, const float* __restrict__ ba2,
    const float* __restrict__ whsh)
{
    __shared__ float sW1[RDIM*SDIM];
    __shared__ float sW2[SDIM];
    int tid=threadIdx.x;
    for (int i=tid;i<RDIM*SDIM;i+=256) sW1[i]=Wa1[2*SDIM*SDIM + i];
    for (int i=tid;i<SDIM;i+=256) sW2[i]=Wa2[i];
    __syncthreads();
    int Nv = g_Nv;
    int warp = tid>>5, lane = tid&31;
#pragma unroll
    for (int it=0; it<4; ++it){
        int s = blockIdx.x*32 + warp*4 + it;
        if (s >= Nv*TOPKK) break;
        int jo = g_vdo[s];
        if (jo < 0) continue;
        int vi = s >> 4;
        int jc = g_vdc[s];
        int i  = g_vlist[vi];
        float dx = pos[i*3+0]-pos[jo*3+0];
        float dy = pos[i*3+1]-pos[jo*3+1];
        float dz = pos[i*3+2]-pos[jo*3+2];
        float r = sqrtf(dx*dx+dy*dy+dz*dz);
        float rf[8];
#pragma unroll
        for (int k=0;k<8;k++){ float cc=k*(5.0f/7.0f); float d=r-cc; rf[k]=expf(-4.0f*d*d); }
        if (lane < 8) g_rf[s*RDIM+lane] = rf[lane];
        if (lane==0) g_shd[s] = sh_dot(dx,dy,dz, whsh);
        float sum = 0.f;
#pragma unroll
        for (int u=0;u<4;u++){
            int d = lane + u*32;
            float hv = g_qkp[(size_t)vi*512 + 256 + d] + g_qkp[(size_t)jc*512 + 384 + d];
#pragma unroll
            for (int k=0;k<8;k++) hv += rf[k]*sW1[k*SDIM+d];
            hv = hv>0.f ? hv : 0.f;
            sum += hv*sW2[d];
        }
        sum = wredsum(sum);
        if (lane==0){
            float sc = sum + ba2[0];
            g_sc[s] = sc;
            atomicMax(&g_maxenc[jo], enc(sc));
        }
    }
}

// ----------------- launch 8: softmax denominator ---------------
__global__ void softmax2()
{
    int s = blockIdx.x*blockDim.x + threadIdx.x;
    int Nv = g_Nv;
    if (s >= Nv*TOPKK) return;
    int jo = g_vdo[s];
    if (jo < 0) return;
    float mx = dec(g_maxenc[jo]);
    float e = expf(g_sc[s]-mx);
    g_ex[s] = e;
    atomicAdd(&g_den[jo], e);
}

// ----------------- launch 9: hierarchical messages (real + virtual fused) ------
// blocks [0,4096): real edges (32/block); [4096,6144): virtual edges (32/block)
__global__ __launch_bounds__(256) void msgsH_k(
    const float* __restrict__ pos, const int* __restrict__ ei,
    const float* __restrict__ Whr, const float* __restrict__ whsh)
{
    __shared__ float sW[RDIM*DIM2];
    __shared__ float swsh[LDIM];
    int tid=threadIdx.x;
    for (int i=tid;i<RDIM*DIM2;i+=256) sW[i]=Whr[i];
    if (tid<LDIM) swsh[tid]=whsh[tid];
    __syncthreads();
    int warp = tid>>5, lane = tid&31;
    int base = lane*8;
    int b = blockIdx.x;
    if (b < 4096){
#pragma unroll
        for (int it=0; it<4; ++it){
            int e = b*32 + warp*4 + it;
            int src = ei[e], dst = ei[E_EDGES+e];
            if (!(g_mf[src] & g_mf[dst])) continue;
            float dx = pos[src*3+0]-pos[dst*3+0];
            float dy = pos[src*3+1]-pos[dst*3+1];
            float dz = pos[src*3+2]-pos[dst*3+2];
            float r = sqrtf(dx*dx+dy*dy+dz*dz);
            float shd = sh_dot(dx,dy,dz, swsh);
            float rf[8];
#pragma unroll
            for (int k=0;k<8;k++){ float cc=k*(5.0f/7.0f); float d=r-cc; rf[k]=expf(-4.0f*d*d); }
            float g[8];
#pragma unroll
            for (int u=0;u<8;u++){
                float acc=0.f;
#pragma unroll
                for (int k=0;k<8;k++) acc += rf[k]*sW[k*DIM2+base+u];
                g[u]=acc;
            }
            float4 h0 = *(const float4*)&g_hloc[(size_t)src*DIM2+base];
            float4 h1 = *(const float4*)&g_hloc[(size_t)src*DIM2+base+4];
            red4(&g_aggH[(size_t)dst*DIM2+base  ], h0.x*g[0]*shd, h0.y*g[1]*shd, h0.z*g[2]*shd, h0.w*g[3]*shd);
            red4(&g_aggH[(size_t)dst*DIM2+base+4], h1.x*g[4]*shd, h1.y*g[5]*shd, h1.z*g[6]*shd, h1.w*g[7]*shd);
        }
    } else {
        int Nv = g_Nv;
#pragma unroll
        for (int it=0; it<4; ++it){
            int s = (b-4096)*32 + warp*4 + it;
            if (s >= Nv*TOPKK) break;
            int jo = g_vdo[s];
            if (jo < 0) continue;
            int vi = s >> 4;
            int i  = g_vlist[vi];
            float wv = g_ex[s]/(g_den[jo]+1e-12f);
            float shd = g_shd[s];
            float rf[8];
#pragma unroll
            for (int k=0;k<8;k++) rf[k]=g_rf[s*RDIM+k]*wv;
            float g[8];
#pragma unroll
            for (int u=0;u<8;u++){
                float acc=0.f;
#pragma unroll
                for (int k=0;k<8;k++) acc += rf[k]*sW[k*DIM2+base+u];
                g[u]=acc;
            }
            float4 h0 = *(const float4*)&g_hloc[(size_t)i*DIM2+base];
            float4 h1 = *(const float4*)&g_hloc[(size_t)i*DIM2+base+4];
            red4(&g_aggH[(size_t)jo*DIM2+base  ], h0.x*g[0]*shd, h0.y*g[1]*shd, h0.z*g[2]*shd, h0.w*g[3]*shd);
            red4(&g_aggH[(size_t)jo*DIM2+base+4], h1.x*g[4]*shd, h1.y*g[5]*shd, h1.z*g[6]*shd, h1.w*g[7]*shd);
        }
    }
}

// ----------------- launcher ---------------
extern "C" void kernel_launch(void* const* d_in, const int* in_sizes, int n_in,
                              void* d_out, int out_size)
{
    const float* h    = (const float*)d_in[0];
    const float* pos  = (const float*)d_in[1];
    const int*   ei   = (const int*)  d_in[2];
    const float* esh  = (const float*)d_in[3];
    const float* ef   = (const float*)d_in[4];
    const float* Wlr  = (const float*)d_in[6];
    const float* wlsh = (const float*)d_in[7];
    const float* Wlout= (const float*)d_in[8];
    const float* Wpl  = (const float*)d_in[9];
    const float* Wms1 = (const float*)d_in[10];
    const float* bms1 = (const float*)d_in[11];
    const float* Wms2 = (const float*)d_in[12];
    const float* bms2 = (const float*)d_in[13];
    const float* Wq   = (const float*)d_in[14];
    const float* Wk   = (const float*)d_in[15];
    const float* Wa1  = (const float*)d_in[16];
    const float* ba1  = (const float*)d_in[17];
    const float* Wa2  = (const float*)d_in[18];
    const float* ba2  = (const float*)d_in[19];
    const float* Whr  = (const float*)d_in[20];
    const float* whsh = (const float*)d_in[21];
    const float* Whout= (const float*)d_in[22];
    const float* Wph  = (const float*)d_in[23];
    float* out = (float*)d_out;

    float *p_agg1,*p_hloc,*p_qkp,*p_S,*p_aggH,*p_m,*p_Wfl,*p_Wfh,*p_Wcat;
    int *p_Nv,*p_vlist;
    cudaGetSymbolAddress((void**)&p_agg1, g_agg1);
    cudaGetSymbolAddress((void**)&p_hloc, g_hloc);
    cudaGetSymbolAddress((void**)&p_qkp , g_qkp );
    cudaGetSymbolAddress((void**)&p_S   , g_S   );
    cudaGetSymbolAddress((void**)&p_aggH, g_aggH);
    cudaGetSymbolAddress((void**)&p_m   , g_m   );
    cudaGetSymbolAddress((void**)&p_Wfl , g_Wfl );
    cudaGetSymbolAddress((void**)&p_Wfh , g_Wfh );
    cudaGetSymbolAddress((void**)&p_Wcat, g_Wcat);
    cudaGetSymbolAddress((void**)&p_Nv  , g_Nv  );
    cudaGetSymbolAddress((void**)&p_vlist, g_vlist);

    const float scal = 0.088388347648318447f; // 1/sqrt(128)
    const int SMEMSZ = (int)(2*sizeof(TCSmem));   // double-buffered stages

    // allow >48KB dynamic smem (no-op after first call)
    cudaFuncSetAttribute(prep_k, cudaFuncAttributeMaxDynamicSharedMemorySize, SMEMSZ);
    cudaFuncSetAttribute(mask_k, cudaFuncAttributeMaxDynamicSharedMemorySize, SMEMSZ);
    cudaFuncSetAttribute(tcgemm<EPI_ADDPADH,false,false,1>, cudaFuncAttributeMaxDynamicSharedMemorySize, SMEMSZ);
    cudaFuncSetAttribute(tcgemm<EPI_QKP,false,true,1>,      cudaFuncAttributeMaxDynamicSharedMemorySize, SMEMSZ);
    cudaFuncSetAttribute(tcgemm<EPI_SCORES,true,false,2>,   cudaFuncAttributeMaxDynamicSharedMemorySize, SMEMSZ);
    cudaFuncSetAttribute(tcgemm<EPI_FINAL,false,false,1>,   cudaFuncAttributeMaxDynamicSharedMemorySize, SMEMSZ);

    prep_k<<<844,256,SMEMSZ>>>(Wlout,Wpl,Whout,Wph,Wq,Wk,Wa1);
    edge1_k<<<4096,256>>>(h,ei,esh,ef,Wlr,wlsh);
    // h_local = agg1 @ Wfl + pad(h)
    tcgemm<EPI_ADDPADH,false,false,1><<<dim3(4,64),256,SMEMSZ>>>(p_agg1,DIM, p_Wfl,DIM2, p_hloc,DIM2,
        N_NODES,DIM2,DIM, nullptr,nullptr, h,nullptr,0.f);
    // hidden GEMM + m + mf + valid-node scan (last block)
    mask_k<<<64,256,SMEMSZ>>>(Wms1,bms1,Wms2,bms2);
    // fused gathered GEMM: [q | k | P1(+bias) | P2] = hloc_valid @ Wcat
    tcgemm<EPI_QKP,false,true,1><<<dim3(8,64),256,SMEMSZ>>>(p_hloc,DIM2, p_Wcat,512, p_qkp,512,
        N_NODES,512,SDIM, p_Nv, p_vlist, ba1,nullptr,0.f);
    // scores = q @ k^T * scale, diag=NEG (compact Nv x Nv)
    tcgemm<EPI_SCORES,true,false,2><<<dim3(64,32),256,SMEMSZ>>>(p_qkp,512, p_qkp+SDIM,512, p_S,N_NODES,
        N_NODES,N_NODES,SDIM, p_Nv, nullptr, nullptr,nullptr, scal);
    topk_k<<<N_NODES,128>>>();
    vedge_mlp<<<N_NODES*TOPKK/32,256>>>(pos, Wa1, Wa2, ba2, whsh);
    softmax2<<<N_NODES*TOPKK/256,256>>>();
    msgsH_k<<<6144,256>>>(pos,ei,Whr,whsh);
    // out = (1-m)*h_local + m*((aggH@Wfh + h_local)*mf)
    tcgemm<EPI_FINAL,false,false,1><<<dim3(4,64),256,SMEMSZ>>>(p_aggH,DIM2, p_Wfh,DIM2, out,DIM2,
        N_NODES,DIM2,DIM2, nullptr,nullptr, p_hloc, p_m, 0.f);
}